// round 1
// baseline (speedup 1.0000x reference)
#include <cuda_runtime.h>
#include <math.h>

#define B 8
#define N 1024
#define H 16
#define D 64
#define HD 1024

// Scratch: Q,K,V in [B,H,N,D] layout. 32MB each, static device globals (allocation-free).
__device__ float g_Q[B * H * N * D];
__device__ float g_K[B * H * N * D];
__device__ float g_V[B * H * N * D];

// ---------------------------------------------------------------------------
// Kernel 1: fused QKV projection.
//   qkv[m, o] = sum_k hs[m, k] * w[o, k]     (m = b*N+n, o in [0, 3*HD))
//   q gets +q_bias then *1/sqrt(D); v gets +v_bias; scattered to [B,H,N,D].
// 64x64 block tile, 256 threads, 4x4 microtile, K-chunks of 64.
// ---------------------------------------------------------------------------
__global__ __launch_bounds__(256) void qkv_kernel(
    const float* __restrict__ hs,   // [B*N, HD]
    const float* __restrict__ w,    // [3*HD, HD]
    const float* __restrict__ qb,   // [HD]
    const float* __restrict__ vb)   // [HD]
{
    __shared__ float As[64][68];
    __shared__ float Bs[64][68];

    const int tid = threadIdx.x;
    const int tx = tid & 15;
    const int ty = tid >> 4;
    const int m0 = blockIdx.y * 64;
    const int n0 = blockIdx.x * 64;

    float acc[4][4];
#pragma unroll
    for (int i = 0; i < 4; i++)
#pragma unroll
        for (int j = 0; j < 4; j++) acc[i][j] = 0.0f;

    for (int k0 = 0; k0 < HD; k0 += 64) {
#pragma unroll
        for (int p = 0; p < 4; p++) {
            int r = (tid >> 4) + p * 16;     // 0..63
            int c = (tid & 15) * 4;          // 0..60
            float4 a = *(const float4*)&hs[(size_t)(m0 + r) * HD + k0 + c];
            *(float4*)&As[r][c] = a;
            float4 bv = *(const float4*)&w[(size_t)(n0 + r) * HD + k0 + c];
            *(float4*)&Bs[r][c] = bv;
        }
        __syncthreads();

#pragma unroll
        for (int kk = 0; kk < 64; kk += 4) {
            float4 a[4], bb[4];
#pragma unroll
            for (int i = 0; i < 4; i++) a[i] = *(float4*)&As[ty + 16 * i][kk];
#pragma unroll
            for (int j = 0; j < 4; j++) bb[j] = *(float4*)&Bs[tx + 16 * j][kk];
#pragma unroll
            for (int i = 0; i < 4; i++)
#pragma unroll
                for (int j = 0; j < 4; j++) {
                    acc[i][j] += a[i].x * bb[j].x;
                    acc[i][j] += a[i].y * bb[j].y;
                    acc[i][j] += a[i].z * bb[j].z;
                    acc[i][j] += a[i].w * bb[j].w;
                }
        }
        __syncthreads();
    }

#pragma unroll
    for (int i = 0; i < 4; i++) {
        int m = m0 + ty + 16 * i;
        int b = m >> 10;
        int n = m & 1023;
#pragma unroll
        for (int j = 0; j < 4; j++) {
            int o = n0 + tx + 16 * j;        // [0, 3072)
            int seg = o >> 10;
            int hd = o & 1023;
            int h = hd >> 6;
            int d = hd & 63;
            size_t idx = (((size_t)(b * H + h)) * N + n) * D + d;
            float val = acc[i][j];
            if (seg == 0)       g_Q[idx] = (val + qb[hd]) * 0.125f;   // 1/sqrt(64)
            else if (seg == 1)  g_K[idx] = val;
            else                g_V[idx] = val + vb[hd];
        }
    }
}

// ---------------------------------------------------------------------------
// Kernel 2: flash-style attention with fused (rel_pos + rel_2d_pos) bias and
// mask-replace (score -> 1e-8 where mask != 0, softmax still over all keys).
// One block per (b, h, 64-query tile); 16 key tiles of 64; online softmax.
// ---------------------------------------------------------------------------
__global__ __launch_bounds__(256) void attn_kernel(
    const float* __restrict__ rel,   // [H, N, N]
    const float* __restrict__ rel2,  // [H, N, N]
    const int*   __restrict__ mask,  // [B, N]
    float*       __restrict__ out)   // [B, N, HD]
{
    __shared__ float Qs[64][68];
    __shared__ float Ks[64][68];
    __shared__ float Vs[64][68];   // [m][d]
    __shared__ float Ps[64][68];   // [q][m]
    __shared__ int   msk[N];

    const int tid = threadIdx.x;
    const int tx = tid & 15;
    const int ty = tid >> 4;
    const int q0 = blockIdx.x * 64;
    const int h  = blockIdx.y;
    const int b  = blockIdx.z;

    const float* Qg = g_Q + (((size_t)(b * H + h)) * N) * D;
    const float* Kg = g_K + (((size_t)(b * H + h)) * N) * D;
    const float* Vg = g_V + (((size_t)(b * H + h)) * N) * D;
    const float* relh  = rel  + (size_t)h * N * N;
    const float* rel2h = rel2 + (size_t)h * N * N;

    // Load Q tile + mask row
#pragma unroll
    for (int p = 0; p < 4; p++) {
        int r = (tid >> 4) + p * 16;
        int c = (tid & 15) * 4;
        *(float4*)&Qs[r][c] = *(const float4*)&Qg[(size_t)(q0 + r) * D + c];
    }
    for (int i = tid; i < N; i += 256) msk[i] = mask[b * N + i];
    __syncthreads();

    float m_i[4], l_i[4], o_acc[4][4];
#pragma unroll
    for (int i = 0; i < 4; i++) {
        m_i[i] = -INFINITY;
        l_i[i] = 0.0f;
#pragma unroll
        for (int j = 0; j < 4; j++) o_acc[i][j] = 0.0f;
    }

    for (int t = 0; t < 16; t++) {
        const int k0 = t * 64;
        // Load K, V tiles
#pragma unroll
        for (int p = 0; p < 4; p++) {
            int r = (tid >> 4) + p * 16;
            int c = (tid & 15) * 4;
            *(float4*)&Ks[r][c] = *(const float4*)&Kg[(size_t)(k0 + r) * D + c];
            *(float4*)&Vs[r][c] = *(const float4*)&Vg[(size_t)(k0 + r) * D + c];
        }
        __syncthreads();

        // S = Q @ K^T for this tile. rows q = ty+16i, cols k = tx+16j
        float s[4][4];
#pragma unroll
        for (int i = 0; i < 4; i++)
#pragma unroll
            for (int j = 0; j < 4; j++) s[i][j] = 0.0f;

#pragma unroll
        for (int kk = 0; kk < 64; kk += 4) {
            float4 a[4], bb[4];
#pragma unroll
            for (int i = 0; i < 4; i++) a[i] = *(float4*)&Qs[ty + 16 * i][kk];
#pragma unroll
            for (int j = 0; j < 4; j++) bb[j] = *(float4*)&Ks[tx + 16 * j][kk];
#pragma unroll
            for (int i = 0; i < 4; i++)
#pragma unroll
                for (int j = 0; j < 4; j++) {
                    s[i][j] += a[i].x * bb[j].x;
                    s[i][j] += a[i].y * bb[j].y;
                    s[i][j] += a[i].z * bb[j].z;
                    s[i][j] += a[i].w * bb[j].w;
                }
        }

        // bias + mask
#pragma unroll
        for (int i = 0; i < 4; i++) {
            int qg = q0 + ty + 16 * i;
#pragma unroll
            for (int j = 0; j < 4; j++) {
                int kg = k0 + tx + 16 * j;
                float sv = s[i][j] + relh[(size_t)qg * N + kg] + rel2h[(size_t)qg * N + kg];
                if (msk[kg] != 0) sv = 1e-8f;
                s[i][j] = sv;
            }
        }

        // online softmax update
#pragma unroll
        for (int i = 0; i < 4; i++) {
            float rmax = fmaxf(fmaxf(s[i][0], s[i][1]), fmaxf(s[i][2], s[i][3]));
#pragma unroll
            for (int off = 8; off > 0; off >>= 1)
                rmax = fmaxf(rmax, __shfl_xor_sync(0xffffffffu, rmax, off));
            float mn = fmaxf(m_i[i], rmax);
            float scale = __expf(m_i[i] - mn);
            m_i[i] = mn;

            float rsum = 0.0f;
#pragma unroll
            for (int j = 0; j < 4; j++) {
                float p = __expf(s[i][j] - mn);
                rsum += p;
                Ps[ty + 16 * i][tx + 16 * j] = p;
            }
#pragma unroll
            for (int off = 8; off > 0; off >>= 1)
                rsum += __shfl_xor_sync(0xffffffffu, rsum, off);
            l_i[i] = l_i[i] * scale + rsum;
#pragma unroll
            for (int j = 0; j < 4; j++) o_acc[i][j] *= scale;
        }
        __syncthreads();

        // O += P @ V. o cols d = tx+16j. P vectorized along m; V scalar broadcast rows.
#pragma unroll
        for (int mm = 0; mm < 64; mm += 4) {
            float4 pv[4];
#pragma unroll
            for (int i = 0; i < 4; i++) pv[i] = *(float4*)&Ps[ty + 16 * i][mm];
#pragma unroll
            for (int q = 0; q < 4; q++) {
                float vv[4];
#pragma unroll
                for (int j = 0; j < 4; j++) vv[j] = Vs[mm + q][tx + 16 * j];
#pragma unroll
                for (int i = 0; i < 4; i++) {
                    float pq = (q == 0) ? pv[i].x : (q == 1) ? pv[i].y : (q == 2) ? pv[i].z : pv[i].w;
#pragma unroll
                    for (int j = 0; j < 4; j++) o_acc[i][j] += pq * vv[j];
                }
            }
        }
        __syncthreads();
    }

    // finalize + write out[b, n, h*64+d]
#pragma unroll
    for (int i = 0; i < 4; i++) {
        int n = q0 + ty + 16 * i;
        float inv = 1.0f / l_i[i];
#pragma unroll
        for (int j = 0; j < 4; j++) {
            int d = tx + 16 * j;
            out[((size_t)b * N + n) * HD + h * D + d] = o_acc[i][j] * inv;
        }
    }
}

extern "C" void kernel_launch(void* const* d_in, const int* in_sizes, int n_in,
                              void* d_out, int out_size)
{
    (void)in_sizes; (void)n_in; (void)out_size;
    const float* hs   = (const float*)d_in[0];   // [B,N,HD]
    const float* w    = (const float*)d_in[1];   // [3HD, HD]
    const float* qb   = (const float*)d_in[2];   // [1,1,HD]
    const float* vb   = (const float*)d_in[3];   // [1,1,HD]
    const float* rel  = (const float*)d_in[4];   // [1,H,N,N]
    const float* rel2 = (const float*)d_in[5];   // [1,H,N,N]
    const int*   mask = (const int*)d_in[6];     // [B,1,1,N]
    float* out = (float*)d_out;                  // [B,N,HD]

    dim3 g1(3 * HD / 64, (B * N) / 64);          // (48, 128)
    qkv_kernel<<<g1, 256>>>(hs, w, qb, vb);

    dim3 g2(N / 64, H, B);                       // (16, 16, 8)
    attn_kernel<<<g2, 256>>>(rel, rel2, mask, out);
}